// round 15
// baseline (speedup 1.0000x reference)
#include <cuda_runtime.h>
#include <cuda_fp16.h>
#include <math_constants.h>
#include <cstdint>
#include <cstddef>

#define B_SZ 8
#define S_SZ 1024
#define D_SZ 1024
#define H_SZ 16
#define DK_SZ 64
#define MROWS (B_SZ * S_SZ)   /* 8192 */
#define WN (D_SZ * D_SZ)
#define AN (MROWS * D_SZ)

// ---------------------------------------------------------------------------
// Scratch (allocation-free rule: __device__ globals)
// ---------------------------------------------------------------------------
__device__ __half g_w16[4][WN];
__device__ __half g_x16[3][AN];           // f16 copies of q,k,v inputs
__device__ __half g_q16[AN];
__device__ __half g_k16[AN];
__device__ __half g_vt16[AN];             // [b*h][d][s]
__device__ __half g_att16[AN];

// ---------------------------------------------------------------------------
__device__ __forceinline__ uint32_t smem_u32(const void* p) {
    uint32_t a;
    asm("{ .reg .u64 t; cvta.to.shared.u64 t, %1; cvt.u32.u64 %0, t; }"
        : "=r"(a) : "l"(p));
    return a;
}
__device__ __forceinline__ void cp_async16(uint32_t dst, const void* src) {
    asm volatile("cp.async.cg.shared.global [%0], [%1], 16;\n"
                 :: "r"(dst), "l"(src) : "memory");
}
#define CP_COMMIT() asm volatile("cp.async.commit_group;\n" ::: "memory")
#define CP_WAIT(n)  asm volatile("cp.async.wait_group %0;\n" :: "n"(n) : "memory")
__device__ __forceinline__ void cp_wait_dyn(bool last) {
    if (last) asm volatile("cp.async.wait_group 0;\n" ::: "memory");
    else      asm volatile("cp.async.wait_group 1;\n" ::: "memory");
}

__device__ __forceinline__ void ldsm_x4(uint32_t& r0, uint32_t& r1,
                                        uint32_t& r2, uint32_t& r3, uint32_t a) {
    asm volatile("ldmatrix.sync.aligned.m8n8.x4.shared.b16 {%0,%1,%2,%3}, [%4];"
                 : "=r"(r0), "=r"(r1), "=r"(r2), "=r"(r3) : "r"(a));
}
__device__ __forceinline__ void mma16816(
    float& d0, float& d1, float& d2, float& d3,
    uint32_t a0, uint32_t a1, uint32_t a2, uint32_t a3,
    uint32_t b0, uint32_t b1)
{
    asm volatile(
        "mma.sync.aligned.m16n8k16.row.col.f32.f16.f16.f32 "
        "{%0,%1,%2,%3}, {%4,%5,%6,%7}, {%8,%9}, {%0,%1,%2,%3};\n"
        : "+f"(d0), "+f"(d1), "+f"(d2), "+f"(d3)
        : "r"(a0), "r"(a1), "r"(a2), "r"(a3), "r"(b0), "r"(b1));
}
// pack two f32 -> f16x2 reg: low half = first arg
__device__ __forceinline__ uint32_t pack_f16(float lo, float hi) {
    uint32_t r;
    asm("cvt.rn.f16x2.f32 %0, %1, %2;" : "=r"(r) : "f"(hi), "f"(lo));
    return r;
}
__device__ __forceinline__ float ex2f(float x) {
    float y; asm("ex2.approx.ftz.f32 %0, %1;" : "=f"(y) : "f"(x)); return y;
}
__device__ __forceinline__ uint32_t ex2_f16x2(uint32_t x) {
    uint32_t y; asm("ex2.approx.f16x2 %0, %1;" : "=r"(y) : "r"(x)); return y;
}

// ---------------------------------------------------------------------------
// fp32 -> f16 conversions
// ---------------------------------------------------------------------------
__global__ __launch_bounds__(256) void cvt_w(
    const float* __restrict__ w0, const float* __restrict__ w1,
    const float* __restrict__ w2, const float* __restrict__ w3,
    __half* __restrict__ y)
{
    const int z = blockIdx.y;
    const float* x = (z == 0) ? w0 : (z == 1) ? w1 : (z == 2) ? w2 : w3;
    int i = blockIdx.x * blockDim.x + threadIdx.x;
    float4 v = ((const float4*)x)[i];
    ((uint2*)(y + (size_t)z * WN))[i] =
        make_uint2(pack_f16(v.x, v.y), pack_f16(v.z, v.w));
}

__global__ __launch_bounds__(256) void cvt_act(
    const float* __restrict__ q, const float* __restrict__ k,
    const float* __restrict__ v, __half* __restrict__ y)
{
    const int z = blockIdx.y;
    const float* x = (z == 0) ? q : (z == 1) ? k : v;
    int i = blockIdx.x * blockDim.x + threadIdx.x;
    float4 t = ((const float4*)x)[i];
    ((uint2*)(y + (size_t)z * AN))[i] =
        make_uint2(pack_f16(t.x, t.y), pack_f16(t.z, t.w));
}

// ---------------------------------------------------------------------------
// GEMM geometry: block tile 128(M) x 64(N), BK=32, 256 threads, 8 warps
// as 4(M) x 2(N); warp tile 32x32. 3-stage cp.async, 1 barrier/chunk.
// ---------------------------------------------------------------------------
#define GPAD 40
#define ATILE_B (128 * GPAD * 2)            /* 10240 */
#define WTILE_B (64 * GPAD * 2)             /* 5120 */
#define STAGEB (ATILE_B + WTILE_B)          /* 15360 */
#define GEMM_SMEM_BYTES (3 * STAGEB)        /* 46080 */
#define VPAD 136

// ---------------------------------------------------------------------------
// Fused QKV projection GEMM (unchanged).
// ---------------------------------------------------------------------------
__global__ __launch_bounds__(256, 3) void qkv_gemm(
    const __half* __restrict__ x16, const __half* __restrict__ w16,
    const float* __restrict__ bq, const float* __restrict__ bk,
    const float* __restrict__ bv,
    const float* __restrict__ ct, const float* __restrict__ st,
    __half* __restrict__ q16, __half* __restrict__ k16,
    __half* __restrict__ vt16)
{
    extern __shared__ char smc[];
    const uint32_t sb = smem_u32(smc);

    const int tid = threadIdx.x;
    const int wid = tid >> 5, lane = tid & 31;
    const int group = lane >> 2, tig = lane & 3;
    const int wm = wid & 3, wn = wid >> 2;
    const int bn = blockIdx.x;
    const int bm = blockIdx.y * 128;
    const int z = blockIdx.z;

    const __half* A16 = x16 + (size_t)z * AN;
    const __half* W = w16 + (size_t)z * WN;
    const float* bias = (z == 0) ? bq : (z == 1) ? bk : bv;

    const uint32_t aln = (uint32_t)((((lane & 7) + ((lane >> 3) & 1) * 8) * GPAD
                                    + (lane >> 4) * 8) * 2);
    const uint32_t bln = (uint32_t)((((lane & 7) + (lane >> 4) * 8) * GPAD
                                    + ((lane >> 3) & 1) * 8) * 2);

    float acc[2][4][4];
#pragma unroll
    for (int i = 0; i < 2; i++)
#pragma unroll
        for (int j = 0; j < 4; j++)
#pragma unroll
            for (int r = 0; r < 4; r++) acc[i][j][r] = 0.f;

    auto cpAW = [&](int c, int s) {
        const int k0 = c * 32;
        const uint32_t base = sb + (uint32_t)s * STAGEB;
#pragma unroll
        for (int it = 0; it < 2; ++it) {
            int idx = tid + it * 256;
            int r = idx >> 2, c4 = idx & 3;
            cp_async16(base + (uint32_t)((r * GPAD + c4 * 8) * 2),
                       A16 + (size_t)(bm + r) * D_SZ + k0 + c4 * 8);
        }
        {
            int r = tid >> 2, c4 = tid & 3;
            int grow;
            if (z < 2) {
                int wn_l = r >> 5, inner = r & 31;
                grow = (inner < 16) ? (bn * 32 + wn_l * 16 + inner)
                                    : (512 + bn * 32 + wn_l * 16 + (inner - 16));
            } else {
                grow = bn * 64 + r;
            }
            cp_async16(base + (uint32_t)ATILE_B + (uint32_t)((r * GPAD + c4 * 8) * 2),
                       W + (size_t)grow * D_SZ + k0 + c4 * 8);
        }
    };

    cpAW(0, 0); CP_COMMIT();
    cpAW(1, 1); CP_COMMIT();

    for (int c = 0; c < 32; ++c) {
        const int s = c % 3;
        cp_wait_dyn(c == 31);
        __syncthreads();
        if (c + 2 < 32) { cpAW(c + 2, (c + 2) % 3); CP_COMMIT(); }

        const uint32_t aB = sb + (uint32_t)s * STAGEB;
        const uint32_t wB = aB + (uint32_t)ATILE_B;
#pragma unroll
        for (int ks = 0; ks < 2; ++ks) {
            uint32_t aF[2][4];
#pragma unroll
            for (int mt = 0; mt < 2; ++mt)
                ldsm_x4(aF[mt][0], aF[mt][1], aF[mt][2], aF[mt][3],
                        aB + (uint32_t)(((wm * 32 + mt * 16) * GPAD + ks * 16) * 2) + aln);
#pragma unroll
            for (int np = 0; np < 2; ++np) {
                uint32_t b0, b1, b2, b3;
                ldsm_x4(b0, b1, b2, b3,
                        wB + (uint32_t)(((wn * 32 + np * 16) * GPAD + ks * 16) * 2) + bln);
#pragma unroll
                for (int mt = 0; mt < 2; ++mt) {
                    mma16816(acc[mt][2 * np][0], acc[mt][2 * np][1],
                             acc[mt][2 * np][2], acc[mt][2 * np][3],
                             aF[mt][0], aF[mt][1], aF[mt][2], aF[mt][3], b0, b1);
                    mma16816(acc[mt][2 * np + 1][0], acc[mt][2 * np + 1][1],
                             acc[mt][2 * np + 1][2], acc[mt][2 * np + 1][3],
                             aF[mt][0], aF[mt][1], aF[mt][2], aF[mt][3], b2, b3);
                }
            }
        }
    }
    __syncthreads();

    if (z < 2) {
        __half* dst16 = (z == 0) ? q16 : k16;
#pragma unroll
        for (int mt = 0; mt < 2; ++mt) {
#pragma unroll
            for (int nt = 0; nt < 2; ++nt) {
                const int dl = bn * 32 + wn * 16 + nt * 8 + tig * 2;
                const int du = dl + 512;
                const float bl0 = bias[dl], bl1 = bias[dl + 1];
                const float bu0 = bias[du], bu1 = bias[du + 1];
#pragma unroll
                for (int rr = 0; rr < 2; ++rr) {
                    const int m = bm + wm * 32 + mt * 16 + group + rr * 8;
                    const int sq = m & (S_SZ - 1);
                    const float xl0 = acc[mt][nt][2 * rr]     + bl0;
                    const float xl1 = acc[mt][nt][2 * rr + 1] + bl1;
                    const float xu0 = acc[mt][nt + 2][2 * rr]     + bu0;
                    const float xu1 = acc[mt][nt + 2][2 * rr + 1] + bu1;
                    const float2 cl = *(const float2*)(ct + (size_t)sq * D_SZ + dl);
                    const float2 sl = *(const float2*)(st + (size_t)sq * D_SZ + dl);
                    const float2 cu = *(const float2*)(ct + (size_t)sq * D_SZ + du);
                    const float2 su = *(const float2*)(st + (size_t)sq * D_SZ + du);
                    const float ol0 = xl0 * cl.x - xu0 * sl.x;
                    const float ol1 = xl1 * cl.y - xu1 * sl.y;
                    const float ou0 = xu0 * cu.x + xl0 * su.x;
                    const float ou1 = xu1 * cu.y + xl1 * su.y;
                    *(uint32_t*)(dst16 + (size_t)m * D_SZ + dl) = pack_f16(ol0, ol1);
                    *(uint32_t*)(dst16 + (size_t)m * D_SZ + du) = pack_f16(ou0, ou1);
                }
            }
        }
    } else {
        __half* sv = (__half*)smc;
#pragma unroll
        for (int mt = 0; mt < 2; ++mt) {
#pragma unroll
            for (int nt = 0; nt < 4; ++nt) {
                const int c = wn * 32 + nt * 8 + tig * 2;
                const float b0 = bias[bn * 64 + c], b1 = bias[bn * 64 + c + 1];
                const int m0 = wm * 32 + mt * 16 + group;
                sv[(c)     * VPAD + m0]     = __float2half_rn(acc[mt][nt][0] + b0);
                sv[(c + 1) * VPAD + m0]     = __float2half_rn(acc[mt][nt][1] + b1);
                sv[(c)     * VPAD + m0 + 8] = __float2half_rn(acc[mt][nt][2] + b0);
                sv[(c + 1) * VPAD + m0 + 8] = __float2half_rn(acc[mt][nt][3] + b1);
            }
        }
        __syncthreads();
        const int b = bm >> 10;
        const int sbase = bm & (S_SZ - 1);
#pragma unroll
        for (int it = 0; it < 4; ++it) {
            const int idx = tid + it * 256;
            const int n = idx >> 4, seg = idx & 15;
            uint4 vv = *(const uint4*)(sv + n * VPAD + seg * 8);
            const int dg = bn * 64 + n;
            const int h = dg >> 6, dk = dg & 63;
            *(uint4*)(vt16 + ((size_t)((b * 16 + h) * 64 + dk)) * S_SZ + sbase + seg * 8) = vv;
        }
    }
}

// ---------------------------------------------------------------------------
// Output GEMM (unchanged).
// ---------------------------------------------------------------------------
__global__ __launch_bounds__(256, 3) void gemm_out(
    const __half* __restrict__ A16, const __half* __restrict__ W,
    const float* __restrict__ bias, float* __restrict__ C)
{
    extern __shared__ char smc[];
    const uint32_t sb = smem_u32(smc);

    const int tid = threadIdx.x;
    const int wid = tid >> 5, lane = tid & 31;
    const int group = lane >> 2, tig = lane & 3;
    const int wm = wid & 3, wn = wid >> 2;
    const int bm = blockIdx.y * 128;
    const int bn = blockIdx.x * 64;

    const uint32_t aln = (uint32_t)((((lane & 7) + ((lane >> 3) & 1) * 8) * GPAD
                                    + (lane >> 4) * 8) * 2);
    const uint32_t bln = (uint32_t)((((lane & 7) + (lane >> 4) * 8) * GPAD
                                    + ((lane >> 3) & 1) * 8) * 2);

    float acc[2][4][4];
#pragma unroll
    for (int i = 0; i < 2; i++)
#pragma unroll
        for (int j = 0; j < 4; j++)
#pragma unroll
            for (int r = 0; r < 4; r++) acc[i][j][r] = 0.f;

    auto cpAW = [&](int c, int s) {
        const int k0 = c * 32;
        const uint32_t base = sb + (uint32_t)s * STAGEB;
#pragma unroll
        for (int it = 0; it < 2; ++it) {
            int idx = tid + it * 256;
            int r = idx >> 2, c4 = idx & 3;
            cp_async16(base + (uint32_t)((r * GPAD + c4 * 8) * 2),
                       A16 + (size_t)(bm + r) * D_SZ + k0 + c4 * 8);
        }
        {
            int r = tid >> 2, c4 = tid & 3;
            cp_async16(base + (uint32_t)ATILE_B + (uint32_t)((r * GPAD + c4 * 8) * 2),
                       W + (size_t)(bn + r) * D_SZ + k0 + c4 * 8);
        }
    };

    cpAW(0, 0); CP_COMMIT();
    cpAW(1, 1); CP_COMMIT();

    for (int c = 0; c < 32; ++c) {
        const int s = c % 3;
        cp_wait_dyn(c == 31);
        __syncthreads();
        if (c + 2 < 32) { cpAW(c + 2, (c + 2) % 3); CP_COMMIT(); }

        const uint32_t aB = sb + (uint32_t)s * STAGEB;
        const uint32_t wB = aB + (uint32_t)ATILE_B;
#pragma unroll
        for (int ks = 0; ks < 2; ++ks) {
            uint32_t aF[2][4];
#pragma unroll
            for (int mt = 0; mt < 2; ++mt)
                ldsm_x4(aF[mt][0], aF[mt][1], aF[mt][2], aF[mt][3],
                        aB + (uint32_t)(((wm * 32 + mt * 16) * GPAD + ks * 16) * 2) + aln);
#pragma unroll
            for (int np = 0; np < 2; ++np) {
                uint32_t b0, b1, b2, b3;
                ldsm_x4(b0, b1, b2, b3,
                        wB + (uint32_t)(((wn * 32 + np * 16) * GPAD + ks * 16) * 2) + bln);
#pragma unroll
                for (int mt = 0; mt < 2; ++mt) {
                    mma16816(acc[mt][2 * np][0], acc[mt][2 * np][1],
                             acc[mt][2 * np][2], acc[mt][2 * np][3],
                             aF[mt][0], aF[mt][1], aF[mt][2], aF[mt][3], b0, b1);
                    mma16816(acc[mt][2 * np + 1][0], acc[mt][2 * np + 1][1],
                             acc[mt][2 * np + 1][2], acc[mt][2 * np + 1][3],
                             aF[mt][0], aF[mt][1], aF[mt][2], aF[mt][3], b2, b3);
                }
            }
        }
    }

#pragma unroll
    for (int mt = 0; mt < 2; ++mt) {
        const int m0 = bm + wm * 32 + mt * 16 + group;
#pragma unroll
        for (int nt = 0; nt < 4; ++nt) {
            const int col = bn + wn * 32 + nt * 8 + tig * 2;
            const float bx = bias[col], by = bias[col + 1];
            *(float2*)(C + (size_t)m0 * D_SZ + col) =
                make_float2(acc[mt][nt][0] + bx, acc[mt][nt][1] + by);
            *(float2*)(C + (size_t)(m0 + 8) * D_SZ + col) =
                make_float2(acc[mt][nt][2] + bx, acc[mt][nt][3] + by);
        }
    }
}

// ---------------------------------------------------------------------------
// Flash attention — f16x2 exp + row-sum-by-MMA (ones fragment), 3-stage
// cp.async, rescale skip. One block = (b,h) x 128 q rows, 8 warps.
// ---------------------------------------------------------------------------
#define APAD 72
#define ATILEB (64 * APAD * 2)               /* 9216 */
#define ASTAGEB (2 * ATILEB)                 /* K + V per stage */
#define ATTN_SMEM_BYTES (3 * ASTAGEB)        /* 55296 */

__global__ __launch_bounds__(256, 2) void attn_mma(
    const __half* __restrict__ q16_, const __half* __restrict__ k16_,
    const __half* __restrict__ vt16_,
    const float* __restrict__ mask, const float* __restrict__ prior_bias,
    __half* __restrict__ out16)
{
    extern __shared__ char asm_[];
    const uint32_t sb = smem_u32(asm_);

    const int tid = threadIdx.x;
    const int wid = tid >> 5, lane = tid & 31;
    const int group = lane >> 2, tig = lane & 3;
    const int bh = blockIdx.y, b = bh >> 4, h = bh & 15;
    const int q0 = blockIdx.x * 128;

    const uint32_t bln = (uint32_t)((((lane & 7) + (lane >> 4) * 8) * APAD
                                    + ((lane >> 3) & 1) * 8) * 2);
    // ones-column B fragment (n = 0 only): f16 1.0 pairs in group-0 threads
    const uint32_t onesB = (group == 0) ? 0x3C003C00u : 0u;

    const float LOG2E = 1.4426950408889634f;
    float sig = 1.0f / (1.0f + __expf(-prior_bias[h]));
    sig *= LOG2E;
    const float scale = 0.125f * LOG2E;

    uint32_t qh[4][4];
    const int r0 = wid * 16 + group;
    {
        const size_t rowa = (size_t)(b * S_SZ + q0 + r0) * D_SZ + h * DK_SZ;
        const size_t rowb = rowa + 8 * D_SZ;
#pragma unroll
        for (int ks = 0; ks < 4; ++ks) {
            const int d0 = ks * 16 + tig * 2;
            qh[ks][0] = *(const uint32_t*)(q16_ + rowa + d0);
            qh[ks][1] = *(const uint32_t*)(q16_ + rowb + d0);
            qh[ks][2] = *(const uint32_t*)(q16_ + rowa + d0 + 8);
            qh[ks][3] = *(const uint32_t*)(q16_ + rowb + d0 + 8);
        }
    }

    auto stage = [&](int kt, int s) {
        const int k0 = kt * 64;
#pragma unroll
        for (int it = 0; it < 4; ++it) {
            const int tile = it >> 1;                       // 0 k, 1 vt
            const int idx = (it & 1) * 256 + tid;
            const int r = idx >> 3, c8 = idx & 7;
            const __half* src;
            uint32_t dst;
            if (tile == 0) {
                src = k16_ + (size_t)(b * S_SZ + k0 + r) * D_SZ + h * DK_SZ + c8 * 8;
                dst = sb + (uint32_t)(s * ASTAGEB);
            } else {
                src = vt16_ + (size_t)(bh * 64 + r) * S_SZ + k0 + c8 * 8;
                dst = sb + (uint32_t)ATILEB + (uint32_t)(s * ASTAGEB);
            }
            cp_async16(dst + (uint32_t)((r * APAD + c8 * 8) * 2), src);
        }
    };

    float o[8][4];
#pragma unroll
    for (int i = 0; i < 8; i++)
#pragma unroll
        for (int j = 0; j < 4; j++) o[i][j] = 0.f;
    float accl[4] = {0.f, 0.f, 0.f, 0.f};    // l via ones-MMA (col 0, tig==0)
    float m0 = -1e30f, m1 = -1e30f;
    const float qr0f = (float)(q0 + r0);
    const float qr1f = qr0f + 8.f;

    stage(0, 0); CP_COMMIT();
    stage(1, 1); CP_COMMIT();

    for (int kt = 0; kt < S_SZ / 64; ++kt) {
        const int s = kt % 3;
        const int k0 = kt * 64;
        cp_wait_dyn(kt == S_SZ / 64 - 1);
        __syncthreads();
        if (kt + 2 < S_SZ / 64) { stage(kt + 2, (kt + 2) % 3); CP_COMMIT(); }

        const uint32_t kB = sb + (uint32_t)(s * ASTAGEB);
        const uint32_t vB = sb + (uint32_t)ATILEB + (uint32_t)(s * ASTAGEB);

        float sc[8][4];
#pragma unroll
        for (int i = 0; i < 8; i++)
#pragma unroll
            for (int j = 0; j < 4; j++) sc[i][j] = 0.f;
#pragma unroll
        for (int ks = 0; ks < 4; ++ks) {
#pragma unroll
            for (int np = 0; np < 4; ++np) {
                uint32_t b0, b1, b2, b3;
                ldsm_x4(b0, b1, b2, b3,
                        kB + (uint32_t)(((np * 16) * APAD + ks * 16) * 2) + bln);
                mma16816(sc[2 * np][0], sc[2 * np][1], sc[2 * np][2], sc[2 * np][3],
                         qh[ks][0], qh[ks][1], qh[ks][2], qh[ks][3], b0, b1);
                mma16816(sc[2 * np + 1][0], sc[2 * np + 1][1],
                         sc[2 * np + 1][2], sc[2 * np + 1][3],
                         qh[ks][0], qh[ks][1], qh[ks][2], qh[ks][3], b2, b3);
            }
        }

        float mx0 = -1e30f, mx1 = -1e30f;
#pragma unroll
        for (int nt = 0; nt < 8; ++nt) {
            const int kl = nt * 8 + tig * 2;
            const float kf0 = (float)(k0 + kl), kf1 = kf0 + 1.f;
            const float mk0 = __ldg(mask + b * S_SZ + k0 + kl) * LOG2E;
            const float mk1 = __ldg(mask + b * S_SZ + k0 + kl + 1) * LOG2E;
            sc[nt][0] = sc[nt][0] * scale + mk0 - sig * fabsf(qr0f - kf0);
            sc[nt][1] = sc[nt][1] * scale + mk1 - sig * fabsf(qr0f - kf1);
            sc[nt][2] = sc[nt][2] * scale + mk0 - sig * fabsf(qr1f - kf0);
            sc[nt][3] = sc[nt][3] * scale + mk1 - sig * fabsf(qr1f - kf1);
            mx0 = fmaxf(mx0, fmaxf(sc[nt][0], sc[nt][1]));
            mx1 = fmaxf(mx1, fmaxf(sc[nt][2], sc[nt][3]));
        }
        mx0 = fmaxf(mx0, __shfl_xor_sync(0xffffffffu, mx0, 1));
        mx0 = fmaxf(mx0, __shfl_xor_sync(0xffffffffu, mx0, 2));
        mx1 = fmaxf(mx1, __shfl_xor_sync(0xffffffffu, mx1, 1));
        mx1 = fmaxf(mx1, __shfl_xor_sync(0xffffffffu, mx1, 2));

        // ---- rescale history only if some row's max advanced (warp-uniform)
        const bool upd = (mx0 > m0) || (mx1 > m1);
        if (__any_sync(0xffffffffu, upd)) {
            const float nm0 = fmaxf(m0, mx0), nm1 = fmaxf(m1, mx1);
            const float a0 = ex2f(m0 - nm0), a1 = ex2f(m1 - nm1);
            m0 = nm0; m1 = nm1;
            accl[0] *= a0; accl[1] *= a0; accl[2] *= a1; accl[3] *= a1;
#pragma unroll
            for (int nt = 0; nt < 8; ++nt) {
                o[nt][0] *= a0; o[nt][1] *= a0;
                o[nt][2] *= a1; o[nt][3] *= a1;
            }
        }

        // ---- P fragments: pack (s - m) pairs, exponentiate in f16x2
        uint32_t pa[4][4];
#pragma unroll
        for (int ks = 0; ks < 4; ++ks) {
            pa[ks][0] = ex2_f16x2(pack_f16(sc[2 * ks][0] - m0, sc[2 * ks][1] - m0));
            pa[ks][1] = ex2_f16x2(pack_f16(sc[2 * ks][2] - m1, sc[2 * ks][3] - m1));
            pa[ks][2] = ex2_f16x2(pack_f16(sc[2 * ks + 1][0] - m0, sc[2 * ks + 1][1] - m0));
            pa[ks][3] = ex2_f16x2(pack_f16(sc[2 * ks + 1][2] - m1, sc[2 * ks + 1][3] - m1));
        }
        // ---- O += P V  and  l += P * ones (extra MMA, constant B fragment)
#pragma unroll
        for (int ks = 0; ks < 4; ++ks) {
#pragma unroll
            for (int np = 0; np < 4; ++np) {
                uint32_t b0, b1, b2, b3;
                ldsm_x4(b0, b1, b2, b3,
                        vB + (uint32_t)(((np * 16) * APAD + ks * 16) * 2) + bln);
                mma16816(o[2 * np][0], o[2 * np][1], o[2 * np][2], o[2 * np][3],
                         pa[ks][0], pa[ks][1], pa[ks][2], pa[ks][3], b0, b1);
                mma16816(o[2 * np + 1][0], o[2 * np + 1][1],
                         o[2 * np + 1][2], o[2 * np + 1][3],
                         pa[ks][0], pa[ks][1], pa[ks][2], pa[ks][3], b2, b3);
            }
            mma16816(accl[0], accl[1], accl[2], accl[3],
                     pa[ks][0], pa[ks][1], pa[ks][2], pa[ks][3], onesB, onesB);
        }
    }

    // l lives in column 0 => threads with tig==0, regs accl[0]/accl[2]
    const float l0 = __shfl_sync(0xffffffffu, accl[0], lane & 28);
    const float l1 = __shfl_sync(0xffffffffu, accl[2], lane & 28);
    const float inv0 = 1.0f / l0, inv1 = 1.0f / l1;
    const int gr0 = b * S_SZ + q0 + r0;
#pragma unroll
    for (int nt = 0; nt < 8; ++nt) {
        const int col = h * DK_SZ + nt * 8 + tig * 2;
        *(uint32_t*)(out16 + (size_t)gr0 * D_SZ + col) =
            pack_f16(o[nt][0] * inv0, o[nt][1] * inv0);
        *(uint32_t*)(out16 + (size_t)(gr0 + 8) * D_SZ + col) =
            pack_f16(o[nt][2] * inv1, o[nt][3] * inv1);
    }
}

// ---------------------------------------------------------------------------
extern "C" void kernel_launch(void* const* d_in, const int* in_sizes, int n_in,
                              void* d_out, int out_size)
{
    const float* q     = (const float*)d_in[0];
    const float* k     = (const float*)d_in[1];
    const float* v     = (const float*)d_in[2];
    const float* cosp  = (const float*)d_in[3];
    const float* sinp  = (const float*)d_in[4];
    const float* maskp = (const float*)d_in[5];
    // d_in[6] = short_matrix (analytic: -|i-j|)
    const float* Wq = (const float*)d_in[7];
    const float* bq = (const float*)d_in[8];
    const float* Wk = (const float*)d_in[9];
    const float* bk = (const float*)d_in[10];
    const float* Wv = (const float*)d_in[11];
    const float* bv = (const float*)d_in[12];
    const float* Wo = (const float*)d_in[13];
    const float* bo = (const float*)d_in[14];
    const float* apb = (const float*)d_in[15];

    __half *w16, *x16, *q16, *k16, *vt16, *att16;
    cudaGetSymbolAddress((void**)&w16,   g_w16);
    cudaGetSymbolAddress((void**)&x16,   g_x16);
    cudaGetSymbolAddress((void**)&q16,   g_q16);
    cudaGetSymbolAddress((void**)&k16,   g_k16);
    cudaGetSymbolAddress((void**)&vt16,  g_vt16);
    cudaGetSymbolAddress((void**)&att16, g_att16);

    cudaFuncSetAttribute(qkv_gemm, cudaFuncAttributeMaxDynamicSharedMemorySize,
                         GEMM_SMEM_BYTES);
    cudaFuncSetAttribute(gemm_out, cudaFuncAttributeMaxDynamicSharedMemorySize,
                         GEMM_SMEM_BYTES);
    cudaFuncSetAttribute(attn_mma, cudaFuncAttributeMaxDynamicSharedMemorySize,
                         ATTN_SMEM_BYTES);

    cvt_w<<<dim3(WN / 1024, 4), 256>>>(Wq, Wk, Wv, Wo, w16);
    cvt_act<<<dim3(AN / 1024, 3), 256>>>(q, k, v, x16);

    qkv_gemm<<<dim3(16, 64, 3), 256, GEMM_SMEM_BYTES>>>(
        x16, w16, bq, bk, bv, cosp, sinp, q16, k16, vt16);

    attn_mma<<<dim3(S_SZ / 128, B_SZ * H_SZ), 256, ATTN_SMEM_BYTES>>>(
        q16, k16, vt16, maskp, apb, att16);

    gemm_out<<<dim3(16, 64), 256, GEMM_SMEM_BYTES>>>(
        att16, w16 + 3 * (size_t)WN, bo, (float*)d_out);
}

// round 16
// speedup vs baseline: 1.0352x; 1.0352x over previous
#include <cuda_runtime.h>
#include <cuda_fp16.h>
#include <math_constants.h>
#include <cstdint>
#include <cstddef>

#define B_SZ 8
#define S_SZ 1024
#define D_SZ 1024
#define H_SZ 16
#define DK_SZ 64
#define MROWS (B_SZ * S_SZ)   /* 8192 */
#define WN (D_SZ * D_SZ)
#define AN (MROWS * D_SZ)

// ---------------------------------------------------------------------------
// Scratch (allocation-free rule: __device__ globals)
// ---------------------------------------------------------------------------
__device__ __half g_w16[4][WN];
__device__ __half g_x16[3][AN];           // f16 copies of q,k,v inputs
__device__ __half g_q16[AN];
__device__ __half g_k16[AN];
__device__ __half g_vt16[AN];             // [b*h][d][s]
__device__ __half g_att16[AN];

// ---------------------------------------------------------------------------
__device__ __forceinline__ uint32_t smem_u32(const void* p) {
    uint32_t a;
    asm("{ .reg .u64 t; cvta.to.shared.u64 t, %1; cvt.u32.u64 %0, t; }"
        : "=r"(a) : "l"(p));
    return a;
}
__device__ __forceinline__ void cp_async16(uint32_t dst, const void* src) {
    asm volatile("cp.async.cg.shared.global [%0], [%1], 16;\n"
                 :: "r"(dst), "l"(src) : "memory");
}
#define CP_COMMIT() asm volatile("cp.async.commit_group;\n" ::: "memory")
#define CP_WAIT(n)  asm volatile("cp.async.wait_group %0;\n" :: "n"(n) : "memory")
__device__ __forceinline__ void cp_wait_dyn(bool last) {
    if (last) asm volatile("cp.async.wait_group 0;\n" ::: "memory");
    else      asm volatile("cp.async.wait_group 1;\n" ::: "memory");
}

__device__ __forceinline__ void ldsm_x4(uint32_t& r0, uint32_t& r1,
                                        uint32_t& r2, uint32_t& r3, uint32_t a) {
    asm volatile("ldmatrix.sync.aligned.m8n8.x4.shared.b16 {%0,%1,%2,%3}, [%4];"
                 : "=r"(r0), "=r"(r1), "=r"(r2), "=r"(r3) : "r"(a));
}
__device__ __forceinline__ void mma16816(
    float& d0, float& d1, float& d2, float& d3,
    uint32_t a0, uint32_t a1, uint32_t a2, uint32_t a3,
    uint32_t b0, uint32_t b1)
{
    asm volatile(
        "mma.sync.aligned.m16n8k16.row.col.f32.f16.f16.f32 "
        "{%0,%1,%2,%3}, {%4,%5,%6,%7}, {%8,%9}, {%0,%1,%2,%3};\n"
        : "+f"(d0), "+f"(d1), "+f"(d2), "+f"(d3)
        : "r"(a0), "r"(a1), "r"(a2), "r"(a3), "r"(b0), "r"(b1));
}
// pack two f32 -> f16x2 reg: low half = first arg
__device__ __forceinline__ uint32_t pack_f16(float lo, float hi) {
    uint32_t r;
    asm("cvt.rn.f16x2.f32 %0, %1, %2;" : "=r"(r) : "f"(hi), "f"(lo));
    return r;
}
__device__ __forceinline__ float ex2f(float x) {
    float y; asm("ex2.approx.ftz.f32 %0, %1;" : "=f"(y) : "f"(x)); return y;
}

// ---------------------------------------------------------------------------
// fp32 -> f16 conversions
// ---------------------------------------------------------------------------
__global__ __launch_bounds__(256) void cvt_w(
    const float* __restrict__ w0, const float* __restrict__ w1,
    const float* __restrict__ w2, const float* __restrict__ w3,
    __half* __restrict__ y)
{
    const int z = blockIdx.y;
    const float* x = (z == 0) ? w0 : (z == 1) ? w1 : (z == 2) ? w2 : w3;
    int i = blockIdx.x * blockDim.x + threadIdx.x;
    float4 v = ((const float4*)x)[i];
    ((uint2*)(y + (size_t)z * WN))[i] =
        make_uint2(pack_f16(v.x, v.y), pack_f16(v.z, v.w));
}

__global__ __launch_bounds__(256) void cvt_act(
    const float* __restrict__ q, const float* __restrict__ k,
    const float* __restrict__ v, __half* __restrict__ y)
{
    const int z = blockIdx.y;
    const float* x = (z == 0) ? q : (z == 1) ? k : v;
    int i = blockIdx.x * blockDim.x + threadIdx.x;
    float4 t = ((const float4*)x)[i];
    ((uint2*)(y + (size_t)z * AN))[i] =
        make_uint2(pack_f16(t.x, t.y), pack_f16(t.z, t.w));
}

// ---------------------------------------------------------------------------
// GEMM geometry: block tile 128(M) x 64(N), BK=32, 256 threads, 8 warps
// as 4(M) x 2(N); warp tile 32x32. 3-stage cp.async, 1 barrier/chunk.
// ---------------------------------------------------------------------------
#define GPAD 40
#define ATILE_B (128 * GPAD * 2)            /* 10240 */
#define WTILE_B (64 * GPAD * 2)             /* 5120 */
#define STAGEB (ATILE_B + WTILE_B)          /* 15360 */
#define GEMM_SMEM_BYTES (3 * STAGEB)        /* 46080 */
#define VPAD 136

// ---------------------------------------------------------------------------
// Fused QKV projection GEMM (unchanged).
// ---------------------------------------------------------------------------
__global__ __launch_bounds__(256, 3) void qkv_gemm(
    const __half* __restrict__ x16, const __half* __restrict__ w16,
    const float* __restrict__ bq, const float* __restrict__ bk,
    const float* __restrict__ bv,
    const float* __restrict__ ct, const float* __restrict__ st,
    __half* __restrict__ q16, __half* __restrict__ k16,
    __half* __restrict__ vt16)
{
    extern __shared__ char smc[];
    const uint32_t sb = smem_u32(smc);

    const int tid = threadIdx.x;
    const int wid = tid >> 5, lane = tid & 31;
    const int group = lane >> 2, tig = lane & 3;
    const int wm = wid & 3, wn = wid >> 2;
    const int bn = blockIdx.x;
    const int bm = blockIdx.y * 128;
    const int z = blockIdx.z;

    const __half* A16 = x16 + (size_t)z * AN;
    const __half* W = w16 + (size_t)z * WN;
    const float* bias = (z == 0) ? bq : (z == 1) ? bk : bv;

    const uint32_t aln = (uint32_t)((((lane & 7) + ((lane >> 3) & 1) * 8) * GPAD
                                    + (lane >> 4) * 8) * 2);
    const uint32_t bln = (uint32_t)((((lane & 7) + (lane >> 4) * 8) * GPAD
                                    + ((lane >> 3) & 1) * 8) * 2);

    float acc[2][4][4];
#pragma unroll
    for (int i = 0; i < 2; i++)
#pragma unroll
        for (int j = 0; j < 4; j++)
#pragma unroll
            for (int r = 0; r < 4; r++) acc[i][j][r] = 0.f;

    auto cpAW = [&](int c, int s) {
        const int k0 = c * 32;
        const uint32_t base = sb + (uint32_t)s * STAGEB;
#pragma unroll
        for (int it = 0; it < 2; ++it) {
            int idx = tid + it * 256;
            int r = idx >> 2, c4 = idx & 3;
            cp_async16(base + (uint32_t)((r * GPAD + c4 * 8) * 2),
                       A16 + (size_t)(bm + r) * D_SZ + k0 + c4 * 8);
        }
        {
            int r = tid >> 2, c4 = tid & 3;
            int grow;
            if (z < 2) {
                int wn_l = r >> 5, inner = r & 31;
                grow = (inner < 16) ? (bn * 32 + wn_l * 16 + inner)
                                    : (512 + bn * 32 + wn_l * 16 + (inner - 16));
            } else {
                grow = bn * 64 + r;
            }
            cp_async16(base + (uint32_t)ATILE_B + (uint32_t)((r * GPAD + c4 * 8) * 2),
                       W + (size_t)grow * D_SZ + k0 + c4 * 8);
        }
    };

    cpAW(0, 0); CP_COMMIT();
    cpAW(1, 1); CP_COMMIT();

    for (int c = 0; c < 32; ++c) {
        const int s = c % 3;
        cp_wait_dyn(c == 31);
        __syncthreads();
        if (c + 2 < 32) { cpAW(c + 2, (c + 2) % 3); CP_COMMIT(); }

        const uint32_t aB = sb + (uint32_t)s * STAGEB;
        const uint32_t wB = aB + (uint32_t)ATILE_B;
#pragma unroll
        for (int ks = 0; ks < 2; ++ks) {
            uint32_t aF[2][4];
#pragma unroll
            for (int mt = 0; mt < 2; ++mt)
                ldsm_x4(aF[mt][0], aF[mt][1], aF[mt][2], aF[mt][3],
                        aB + (uint32_t)(((wm * 32 + mt * 16) * GPAD + ks * 16) * 2) + aln);
#pragma unroll
            for (int np = 0; np < 2; ++np) {
                uint32_t b0, b1, b2, b3;
                ldsm_x4(b0, b1, b2, b3,
                        wB + (uint32_t)(((wn * 32 + np * 16) * GPAD + ks * 16) * 2) + bln);
#pragma unroll
                for (int mt = 0; mt < 2; ++mt) {
                    mma16816(acc[mt][2 * np][0], acc[mt][2 * np][1],
                             acc[mt][2 * np][2], acc[mt][2 * np][3],
                             aF[mt][0], aF[mt][1], aF[mt][2], aF[mt][3], b0, b1);
                    mma16816(acc[mt][2 * np + 1][0], acc[mt][2 * np + 1][1],
                             acc[mt][2 * np + 1][2], acc[mt][2 * np + 1][3],
                             aF[mt][0], aF[mt][1], aF[mt][2], aF[mt][3], b2, b3);
                }
            }
        }
    }
    __syncthreads();

    if (z < 2) {
        __half* dst16 = (z == 0) ? q16 : k16;
#pragma unroll
        for (int mt = 0; mt < 2; ++mt) {
#pragma unroll
            for (int nt = 0; nt < 2; ++nt) {
                const int dl = bn * 32 + wn * 16 + nt * 8 + tig * 2;
                const int du = dl + 512;
                const float bl0 = bias[dl], bl1 = bias[dl + 1];
                const float bu0 = bias[du], bu1 = bias[du + 1];
#pragma unroll
                for (int rr = 0; rr < 2; ++rr) {
                    const int m = bm + wm * 32 + mt * 16 + group + rr * 8;
                    const int sq = m & (S_SZ - 1);
                    const float xl0 = acc[mt][nt][2 * rr]     + bl0;
                    const float xl1 = acc[mt][nt][2 * rr + 1] + bl1;
                    const float xu0 = acc[mt][nt + 2][2 * rr]     + bu0;
                    const float xu1 = acc[mt][nt + 2][2 * rr + 1] + bu1;
                    const float2 cl = *(const float2*)(ct + (size_t)sq * D_SZ + dl);
                    const float2 sl = *(const float2*)(st + (size_t)sq * D_SZ + dl);
                    const float2 cu = *(const float2*)(ct + (size_t)sq * D_SZ + du);
                    const float2 su = *(const float2*)(st + (size_t)sq * D_SZ + du);
                    const float ol0 = xl0 * cl.x - xu0 * sl.x;
                    const float ol1 = xl1 * cl.y - xu1 * sl.y;
                    const float ou0 = xu0 * cu.x + xl0 * su.x;
                    const float ou1 = xu1 * cu.y + xl1 * su.y;
                    *(uint32_t*)(dst16 + (size_t)m * D_SZ + dl) = pack_f16(ol0, ol1);
                    *(uint32_t*)(dst16 + (size_t)m * D_SZ + du) = pack_f16(ou0, ou1);
                }
            }
        }
    } else {
        __half* sv = (__half*)smc;
#pragma unroll
        for (int mt = 0; mt < 2; ++mt) {
#pragma unroll
            for (int nt = 0; nt < 4; ++nt) {
                const int c = wn * 32 + nt * 8 + tig * 2;
                const float b0 = bias[bn * 64 + c], b1 = bias[bn * 64 + c + 1];
                const int m0 = wm * 32 + mt * 16 + group;
                sv[(c)     * VPAD + m0]     = __float2half_rn(acc[mt][nt][0] + b0);
                sv[(c + 1) * VPAD + m0]     = __float2half_rn(acc[mt][nt][1] + b1);
                sv[(c)     * VPAD + m0 + 8] = __float2half_rn(acc[mt][nt][2] + b0);
                sv[(c + 1) * VPAD + m0 + 8] = __float2half_rn(acc[mt][nt][3] + b1);
            }
        }
        __syncthreads();
        const int b = bm >> 10;
        const int sbase = bm & (S_SZ - 1);
#pragma unroll
        for (int it = 0; it < 4; ++it) {
            const int idx = tid + it * 256;
            const int n = idx >> 4, seg = idx & 15;
            uint4 vv = *(const uint4*)(sv + n * VPAD + seg * 8);
            const int dg = bn * 64 + n;
            const int h = dg >> 6, dk = dg & 63;
            *(uint4*)(vt16 + ((size_t)((b * 16 + h) * 64 + dk)) * S_SZ + sbase + seg * 8) = vv;
        }
    }
}

// ---------------------------------------------------------------------------
// Output GEMM (unchanged).
// ---------------------------------------------------------------------------
__global__ __launch_bounds__(256, 3) void gemm_out(
    const __half* __restrict__ A16, const __half* __restrict__ W,
    const float* __restrict__ bias, float* __restrict__ C)
{
    extern __shared__ char smc[];
    const uint32_t sb = smem_u32(smc);

    const int tid = threadIdx.x;
    const int wid = tid >> 5, lane = tid & 31;
    const int group = lane >> 2, tig = lane & 3;
    const int wm = wid & 3, wn = wid >> 2;
    const int bm = blockIdx.y * 128;
    const int bn = blockIdx.x * 64;

    const uint32_t aln = (uint32_t)((((lane & 7) + ((lane >> 3) & 1) * 8) * GPAD
                                    + (lane >> 4) * 8) * 2);
    const uint32_t bln = (uint32_t)((((lane & 7) + (lane >> 4) * 8) * GPAD
                                    + ((lane >> 3) & 1) * 8) * 2);

    float acc[2][4][4];
#pragma unroll
    for (int i = 0; i < 2; i++)
#pragma unroll
        for (int j = 0; j < 4; j++)
#pragma unroll
            for (int r = 0; r < 4; r++) acc[i][j][r] = 0.f;

    auto cpAW = [&](int c, int s) {
        const int k0 = c * 32;
        const uint32_t base = sb + (uint32_t)s * STAGEB;
#pragma unroll
        for (int it = 0; it < 2; ++it) {
            int idx = tid + it * 256;
            int r = idx >> 2, c4 = idx & 3;
            cp_async16(base + (uint32_t)((r * GPAD + c4 * 8) * 2),
                       A16 + (size_t)(bm + r) * D_SZ + k0 + c4 * 8);
        }
        {
            int r = tid >> 2, c4 = tid & 3;
            cp_async16(base + (uint32_t)ATILE_B + (uint32_t)((r * GPAD + c4 * 8) * 2),
                       W + (size_t)(bn + r) * D_SZ + k0 + c4 * 8);
        }
    };

    cpAW(0, 0); CP_COMMIT();
    cpAW(1, 1); CP_COMMIT();

    for (int c = 0; c < 32; ++c) {
        const int s = c % 3;
        cp_wait_dyn(c == 31);
        __syncthreads();
        if (c + 2 < 32) { cpAW(c + 2, (c + 2) % 3); CP_COMMIT(); }

        const uint32_t aB = sb + (uint32_t)s * STAGEB;
        const uint32_t wB = aB + (uint32_t)ATILE_B;
#pragma unroll
        for (int ks = 0; ks < 2; ++ks) {
            uint32_t aF[2][4];
#pragma unroll
            for (int mt = 0; mt < 2; ++mt)
                ldsm_x4(aF[mt][0], aF[mt][1], aF[mt][2], aF[mt][3],
                        aB + (uint32_t)(((wm * 32 + mt * 16) * GPAD + ks * 16) * 2) + aln);
#pragma unroll
            for (int np = 0; np < 2; ++np) {
                uint32_t b0, b1, b2, b3;
                ldsm_x4(b0, b1, b2, b3,
                        wB + (uint32_t)(((wn * 32 + np * 16) * GPAD + ks * 16) * 2) + bln);
#pragma unroll
                for (int mt = 0; mt < 2; ++mt) {
                    mma16816(acc[mt][2 * np][0], acc[mt][2 * np][1],
                             acc[mt][2 * np][2], acc[mt][2 * np][3],
                             aF[mt][0], aF[mt][1], aF[mt][2], aF[mt][3], b0, b1);
                    mma16816(acc[mt][2 * np + 1][0], acc[mt][2 * np + 1][1],
                             acc[mt][2 * np + 1][2], acc[mt][2 * np + 1][3],
                             aF[mt][0], aF[mt][1], aF[mt][2], aF[mt][3], b2, b3);
                }
            }
        }
    }

#pragma unroll
    for (int mt = 0; mt < 2; ++mt) {
        const int m0 = bm + wm * 32 + mt * 16 + group;
#pragma unroll
        for (int nt = 0; nt < 4; ++nt) {
            const int col = bn + wn * 32 + nt * 8 + tig * 2;
            const float bx = bias[col], by = bias[col + 1];
            *(float2*)(C + (size_t)m0 * D_SZ + col) =
                make_float2(acc[mt][nt][0] + bx, acc[mt][nt][1] + by);
            *(float2*)(C + (size_t)(m0 + 8) * D_SZ + col) =
                make_float2(acc[mt][nt][2] + bx, acc[mt][nt][3] + by);
        }
    }
}

// ---------------------------------------------------------------------------
// Flash attention — round-14 structure (f32 exp, FADD row sums, rescale
// skip, 3-stage cp.async), plus mask staged in smem (LDG -> LDS).
// One block = one (b,h) x 128 query rows (8 warps, 16 rows each).
// ---------------------------------------------------------------------------
#define APAD 72
#define ATILEB (64 * APAD * 2)               /* 9216 */
#define ASTAGEB (2 * ATILEB)                 /* K + V per stage */
#define AMASK_OFF (3 * ASTAGEB)              /* 55296 */
#define ATTN_SMEM_BYTES (AMASK_OFF + S_SZ * 4)  /* 59392 */

__global__ __launch_bounds__(256, 2) void attn_mma(
    const __half* __restrict__ q16_, const __half* __restrict__ k16_,
    const __half* __restrict__ vt16_,
    const float* __restrict__ mask, const float* __restrict__ prior_bias,
    __half* __restrict__ out16)
{
    extern __shared__ char asm_[];
    const uint32_t sb = smem_u32(asm_);
    float* smask = (float*)(asm_ + AMASK_OFF);

    const int tid = threadIdx.x;
    const int wid = tid >> 5, lane = tid & 31;
    const int group = lane >> 2, tig = lane & 3;
    const int bh = blockIdx.y, b = bh >> 4, h = bh & 15;
    const int q0 = blockIdx.x * 128;

    const uint32_t bln = (uint32_t)((((lane & 7) + (lane >> 4) * 8) * APAD
                                    + ((lane >> 3) & 1) * 8) * 2);

    const float LOG2E = 1.4426950408889634f;
    float sig = 1.0f / (1.0f + __expf(-prior_bias[h]));
    sig *= LOG2E;
    const float scale = 0.125f * LOG2E;

    // stage mask row (x LOG2E) into smem; consumed after first loop barrier
    {
        float4 mv = *(const float4*)(mask + b * S_SZ + tid * 4);
        smask[tid * 4 + 0] = mv.x * LOG2E;
        smask[tid * 4 + 1] = mv.y * LOG2E;
        smask[tid * 4 + 2] = mv.z * LOG2E;
        smask[tid * 4 + 3] = mv.w * LOG2E;
    }

    uint32_t qh[4][4];
    const int r0 = wid * 16 + group;
    {
        const size_t rowa = (size_t)(b * S_SZ + q0 + r0) * D_SZ + h * DK_SZ;
        const size_t rowb = rowa + 8 * D_SZ;
#pragma unroll
        for (int ks = 0; ks < 4; ++ks) {
            const int d0 = ks * 16 + tig * 2;
            qh[ks][0] = *(const uint32_t*)(q16_ + rowa + d0);
            qh[ks][1] = *(const uint32_t*)(q16_ + rowb + d0);
            qh[ks][2] = *(const uint32_t*)(q16_ + rowa + d0 + 8);
            qh[ks][3] = *(const uint32_t*)(q16_ + rowb + d0 + 8);
        }
    }

    auto stage = [&](int kt, int s) {
        const int k0 = kt * 64;
#pragma unroll
        for (int it = 0; it < 4; ++it) {
            const int tile = it >> 1;                       // 0 k, 1 vt
            const int idx = (it & 1) * 256 + tid;
            const int r = idx >> 3, c8 = idx & 7;
            const __half* src;
            uint32_t dst;
            if (tile == 0) {
                src = k16_ + (size_t)(b * S_SZ + k0 + r) * D_SZ + h * DK_SZ + c8 * 8;
                dst = sb + (uint32_t)(s * ASTAGEB);
            } else {
                src = vt16_ + (size_t)(bh * 64 + r) * S_SZ + k0 + c8 * 8;
                dst = sb + (uint32_t)ATILEB + (uint32_t)(s * ASTAGEB);
            }
            cp_async16(dst + (uint32_t)((r * APAD + c8 * 8) * 2), src);
        }
    };

    float o[8][4];
#pragma unroll
    for (int i = 0; i < 8; i++)
#pragma unroll
        for (int j = 0; j < 4; j++) o[i][j] = 0.f;
    float m0 = -1e30f, m1 = -1e30f, l0 = 0.f, l1 = 0.f;
    const float qr0f = (float)(q0 + r0);
    const float qr1f = qr0f + 8.f;

    stage(0, 0); CP_COMMIT();
    stage(1, 1); CP_COMMIT();

    for (int kt = 0; kt < S_SZ / 64; ++kt) {
        const int s = kt % 3;
        const int k0 = kt * 64;
        cp_wait_dyn(kt == S_SZ / 64 - 1);
        __syncthreads();
        if (kt + 2 < S_SZ / 64) { stage(kt + 2, (kt + 2) % 3); CP_COMMIT(); }

        const uint32_t kB = sb + (uint32_t)(s * ASTAGEB);
        const uint32_t vB = sb + (uint32_t)ATILEB + (uint32_t)(s * ASTAGEB);

        float sc[8][4];
#pragma unroll
        for (int i = 0; i < 8; i++)
#pragma unroll
            for (int j = 0; j < 4; j++) sc[i][j] = 0.f;
#pragma unroll
        for (int ks = 0; ks < 4; ++ks) {
#pragma unroll
            for (int np = 0; np < 4; ++np) {
                uint32_t b0, b1, b2, b3;
                ldsm_x4(b0, b1, b2, b3,
                        kB + (uint32_t)(((np * 16) * APAD + ks * 16) * 2) + bln);
                mma16816(sc[2 * np][0], sc[2 * np][1], sc[2 * np][2], sc[2 * np][3],
                         qh[ks][0], qh[ks][1], qh[ks][2], qh[ks][3], b0, b1);
                mma16816(sc[2 * np + 1][0], sc[2 * np + 1][1],
                         sc[2 * np + 1][2], sc[2 * np + 1][3],
                         qh[ks][0], qh[ks][1], qh[ks][2], qh[ks][3], b2, b3);
            }
        }

        float mx0 = -1e30f, mx1 = -1e30f;
#pragma unroll
        for (int nt = 0; nt < 8; ++nt) {
            const int kl = nt * 8 + tig * 2;
            const float kf0 = (float)(k0 + kl), kf1 = kf0 + 1.f;
            const float mk0 = smask[k0 + kl];
            const float mk1 = smask[k0 + kl + 1];
            sc[nt][0] = sc[nt][0] * scale + mk0 - sig * fabsf(qr0f - kf0);
            sc[nt][1] = sc[nt][1] * scale + mk1 - sig * fabsf(qr0f - kf1);
            sc[nt][2] = sc[nt][2] * scale + mk0 - sig * fabsf(qr1f - kf0);
            sc[nt][3] = sc[nt][3] * scale + mk1 - sig * fabsf(qr1f - kf1);
            mx0 = fmaxf(mx0, fmaxf(sc[nt][0], sc[nt][1]));
            mx1 = fmaxf(mx1, fmaxf(sc[nt][2], sc[nt][3]));
        }
        mx0 = fmaxf(mx0, __shfl_xor_sync(0xffffffffu, mx0, 1));
        mx0 = fmaxf(mx0, __shfl_xor_sync(0xffffffffu, mx0, 2));
        mx1 = fmaxf(mx1, __shfl_xor_sync(0xffffffffu, mx1, 1));
        mx1 = fmaxf(mx1, __shfl_xor_sync(0xffffffffu, mx1, 2));

        // ---- rescale history only if some row's max advanced (warp-uniform)
        const bool upd = (mx0 > m0) || (mx1 > m1);
        if (__any_sync(0xffffffffu, upd)) {
            const float nm0 = fmaxf(m0, mx0), nm1 = fmaxf(m1, mx1);
            const float a0 = ex2f(m0 - nm0), a1 = ex2f(m1 - nm1);
            m0 = nm0; m1 = nm1;
            l0 *= a0; l1 *= a1;
#pragma unroll
            for (int nt = 0; nt < 8; ++nt) {
                o[nt][0] *= a0; o[nt][1] *= a0;
                o[nt][2] *= a1; o[nt][3] *= a1;
            }
        }

        float sum0 = 0.f, sum1 = 0.f;
#pragma unroll
        for (int nt = 0; nt < 8; ++nt) {
            sc[nt][0] = ex2f(sc[nt][0] - m0);
            sc[nt][1] = ex2f(sc[nt][1] - m0);
            sc[nt][2] = ex2f(sc[nt][2] - m1);
            sc[nt][3] = ex2f(sc[nt][3] - m1);
            sum0 += sc[nt][0] + sc[nt][1];
            sum1 += sc[nt][2] + sc[nt][3];
        }
        sum0 += __shfl_xor_sync(0xffffffffu, sum0, 1);
        sum0 += __shfl_xor_sync(0xffffffffu, sum0, 2);
        sum1 += __shfl_xor_sync(0xffffffffu, sum1, 1);
        sum1 += __shfl_xor_sync(0xffffffffu, sum1, 2);
        l0 += sum0;
        l1 += sum1;

        uint32_t pa[4][4];
#pragma unroll
        for (int ks = 0; ks < 4; ++ks) {
            pa[ks][0] = pack_f16(sc[2 * ks][0], sc[2 * ks][1]);
            pa[ks][1] = pack_f16(sc[2 * ks][2], sc[2 * ks][3]);
            pa[ks][2] = pack_f16(sc[2 * ks + 1][0], sc[2 * ks + 1][1]);
            pa[ks][3] = pack_f16(sc[2 * ks + 1][2], sc[2 * ks + 1][3]);
        }
#pragma unroll
        for (int ks = 0; ks < 4; ++ks) {
#pragma unroll
            for (int np = 0; np < 4; ++np) {
                uint32_t b0, b1, b2, b3;
                ldsm_x4(b0, b1, b2, b3,
                        vB + (uint32_t)(((np * 16) * APAD + ks * 16) * 2) + bln);
                mma16816(o[2 * np][0], o[2 * np][1], o[2 * np][2], o[2 * np][3],
                         pa[ks][0], pa[ks][1], pa[ks][2], pa[ks][3], b0, b1);
                mma16816(o[2 * np + 1][0], o[2 * np + 1][1],
                         o[2 * np + 1][2], o[2 * np + 1][3],
                         pa[ks][0], pa[ks][1], pa[ks][2], pa[ks][3], b2, b3);
            }
        }
    }

    const float inv0 = 1.0f / l0, inv1 = 1.0f / l1;
    const int gr0 = b * S_SZ + q0 + r0;
#pragma unroll
    for (int nt = 0; nt < 8; ++nt) {
        const int col = h * DK_SZ + nt * 8 + tig * 2;
        *(uint32_t*)(out16 + (size_t)gr0 * D_SZ + col) =
            pack_f16(o[nt][0] * inv0, o[nt][1] * inv0);
        *(uint32_t*)(out16 + (size_t)(gr0 + 8) * D_SZ + col) =
            pack_f16(o[nt][2] * inv1, o[nt][3] * inv1);
    }
}

// ---------------------------------------------------------------------------
extern "C" void kernel_launch(void* const* d_in, const int* in_sizes, int n_in,
                              void* d_out, int out_size)
{
    const float* q     = (const float*)d_in[0];
    const float* k     = (const float*)d_in[1];
    const float* v     = (const float*)d_in[2];
    const float* cosp  = (const float*)d_in[3];
    const float* sinp  = (const float*)d_in[4];
    const float* maskp = (const float*)d_in[5];
    // d_in[6] = short_matrix (analytic: -|i-j|)
    const float* Wq = (const float*)d_in[7];
    const float* bq = (const float*)d_in[8];
    const float* Wk = (const float*)d_in[9];
    const float* bk = (const float*)d_in[10];
    const float* Wv = (const float*)d_in[11];
    const float* bv = (const float*)d_in[12];
    const float* Wo = (const float*)d_in[13];
    const float* bo = (const float*)d_in[14];
    const float* apb = (const float*)d_in[15];

    __half *w16, *x16, *q16, *k16, *vt16, *att16;
    cudaGetSymbolAddress((void**)&w16,   g_w16);
    cudaGetSymbolAddress((void**)&x16,   g_x16);
    cudaGetSymbolAddress((void**)&q16,   g_q16);
    cudaGetSymbolAddress((void**)&k16,   g_k16);
    cudaGetSymbolAddress((void**)&vt16,  g_vt16);
    cudaGetSymbolAddress((void**)&att16, g_att16);

    cudaFuncSetAttribute(qkv_gemm, cudaFuncAttributeMaxDynamicSharedMemorySize,
                         GEMM_SMEM_BYTES);
    cudaFuncSetAttribute(gemm_out, cudaFuncAttributeMaxDynamicSharedMemorySize,
                         GEMM_SMEM_BYTES);
    cudaFuncSetAttribute(attn_mma, cudaFuncAttributeMaxDynamicSharedMemorySize,
                         ATTN_SMEM_BYTES);

    cvt_w<<<dim3(WN / 1024, 4), 256>>>(Wq, Wk, Wv, Wo, w16);
    cvt_act<<<dim3(AN / 1024, 3), 256>>>(q, k, v, x16);

    qkv_gemm<<<dim3(16, 64, 3), 256, GEMM_SMEM_BYTES>>>(
        x16, w16, bq, bk, bv, cosp, sinp, q16, k16, vt16);

    attn_mma<<<dim3(S_SZ / 128, B_SZ * H_SZ), 256, ATTN_SMEM_BYTES>>>(
        q16, k16, vt16, maskp, apb, att16);

    gemm_out<<<dim3(16, 64), 256, GEMM_SMEM_BYTES>>>(
        att16, w16 + 3 * (size_t)WN, bo, (float*)d_out);
}